// round 8
// baseline (speedup 1.0000x reference)
#include <cuda_runtime.h>

// BYOL loss: out = 2 - 2 * mean_i( dot(x_i, xt_i) / (max(||x_i||,eps)*max(||xt_i||,eps)) )
// Quasi-persistent: 256 blocks x 256 threads, each warp does 4 rows with
// software-pipelined (prefetch-next-row) loads; last-block-retires reduce.

#define N_ROWS 8192
#define D_DIM  512
#define EPS 1e-8f

#define NTHREADS 256
#define WARPS_PER_BLOCK 8
#define ROWS_PER_WARP 4
#define NBLOCKS (N_ROWS / (WARPS_PER_BLOCK * ROWS_PER_WARP))  // 256

__device__ float g_partial[NBLOCKS];
__device__ unsigned int g_count = 0;

__global__ void __launch_bounds__(NTHREADS, 2) byol_fused_kernel(
    const float* __restrict__ x, const float* __restrict__ xt,
    float* __restrict__ out)
{
    const int t = threadIdx.x;
    const int lane = t & 31;
    const int warp = t >> 5;
    const int gwarp = blockIdx.x * WARPS_PER_BLOCK + warp;
    const int row0 = gwarp * ROWS_PER_WARP;

    const float4* a4 = reinterpret_cast<const float4*>(x  + (size_t)row0 * D_DIM);
    const float4* b4 = reinterpret_cast<const float4*>(xt + (size_t)row0 * D_DIM);
    const int ROW4 = D_DIM / 4;  // 128 float4 per row

    // double-buffered row data: 8 float4 per buffer stage
    float4 A[2][4], B[2][4];

    #pragma unroll
    for (int i = 0; i < 4; i++) A[0][i] = a4[lane + 32 * i];
    #pragma unroll
    for (int i = 0; i < 4; i++) B[0][i] = b4[lane + 32 * i];

    float cos_sum = 0.0f;

    #pragma unroll
    for (int r = 0; r < ROWS_PER_WARP; r++) {
        const int cur = r & 1, nxt = cur ^ 1;

        // prefetch next row before reducing current
        if (r < ROWS_PER_WARP - 1) {
            const float4* an = a4 + (size_t)(r + 1) * ROW4;
            const float4* bn = b4 + (size_t)(r + 1) * ROW4;
            #pragma unroll
            for (int i = 0; i < 4; i++) A[nxt][i] = an[lane + 32 * i];
            #pragma unroll
            for (int i = 0; i < 4; i++) B[nxt][i] = bn[lane + 32 * i];
        }

        float dot = 0.f, aa = 0.f, bb = 0.f;
        #pragma unroll
        for (int i = 0; i < 4; i++) {
            float4 av = A[cur][i], bv = B[cur][i];
            dot += av.x*bv.x + av.y*bv.y + av.z*bv.z + av.w*bv.w;
            aa  += av.x*av.x + av.y*av.y + av.z*av.z + av.w*av.w;
            bb  += bv.x*bv.x + bv.y*bv.y + bv.z*bv.z + bv.w*bv.w;
        }

        #pragma unroll
        for (int off = 16; off > 0; off >>= 1) {
            dot += __shfl_xor_sync(0xFFFFFFFFu, dot, off);
            aa  += __shfl_xor_sync(0xFFFFFFFFu, aa,  off);
            bb  += __shfl_xor_sync(0xFFFFFFFFu, bb,  off);
        }

        float na = fmaxf(sqrtf(aa), EPS);
        float nb = fmaxf(sqrtf(bb), EPS);
        cos_sum += dot / (na * nb);
    }

    // ---- block partial ----
    __shared__ float s_cos[WARPS_PER_BLOCK];
    if (lane == 0) s_cos[warp] = cos_sum;
    __syncthreads();

    __shared__ bool s_last;
    if (t == 0) {
        float p = 0.f;
        #pragma unroll
        for (int i = 0; i < WARPS_PER_BLOCK; i++) p += s_cos[i];
        g_partial[blockIdx.x] = p;
        __threadfence();
        // wraps to 0 when old == NBLOCKS-1 -> self-resets for graph replay
        unsigned int old = atomicInc(&g_count, NBLOCKS - 1);
        s_last = (old == NBLOCKS - 1);
    }
    __syncthreads();

    if (!s_last) return;

    // ---- last block: deterministic reduce of 256 partials ----
    float s = g_partial[t];

    #pragma unroll
    for (int off = 16; off > 0; off >>= 1)
        s += __shfl_xor_sync(0xFFFFFFFFu, s, off);

    __shared__ float s_w[WARPS_PER_BLOCK];
    if (lane == 0) s_w[warp] = s;
    __syncthreads();

    if (t == 0) {
        float v = 0.f;
        #pragma unroll
        for (int i = 0; i < WARPS_PER_BLOCK; i++) v += s_w[i];
        out[0] = 2.0f - 2.0f * (v / (float)N_ROWS);
    }
}

extern "C" void kernel_launch(void* const* d_in, const int* in_sizes, int n_in,
                              void* d_out, int out_size)
{
    const float* x  = (const float*)d_in[0];
    const float* xt = (const float*)d_in[1];
    float* out = (float*)d_out;

    byol_fused_kernel<<<NBLOCKS, NTHREADS>>>(x, xt, out);
}